// round 15
// baseline (speedup 1.0000x reference)
#include <cuda_runtime.h>

// RNN: B=4096, T=512, I=1, H=16, O=1
//   h_t = tanh(x_t*w_ih + b_ih + b_hh + W_hh h_{t-1}), h_0=0
//   out[b] = dot(h_T, w_fc) + b_fc
//
// R15: split-gather + butterfly exchange. Measured law across R2..R14:
// C ~= (SHFL.32 ops per SM per step) + ~60cy chain tail -> cut shuffle ops.
//   - Lane m gathers only ITS half of h: pairs (m&4)+k, k=0..3
//     (4 reg-source 64-bit shuffles = 8 SHFL.32).
//   - Lane computes 4 row-partials over its half: own rows {2m,2m+1}
//     (seeded with the x-term) and xor-4 partner's rows {2(m^4), 2(m^4)+1}.
//   - Partner partials are h-summed, packed, swapped with ONE
//     __shfl_xor(..,4,8) 64-bit (immediate bfly, 2 SHFL.32).
//   - h = tanh(own_partial + received).  10 SHFL.32/warp-step vs 16.
// Mapping kept: 8 lanes/element, lane m owns rows {2m,2m+1} packed f32x2;
// 4 elements/warp; 1024 single-warp blocks; x staged in smem;
// tanh.approx.f32; f32 datapath (fp16 failed the gate in R11).

#define RNN_B 4096
#define RNN_T 512
#define RNN_H 16
#define XROW (RNN_T + 4)   // x row pad: groups' reads on distinct banks

__device__ __forceinline__ float tanh_approx(float x) {
    float y; asm("tanh.approx.f32 %0, %1;" : "=f"(y) : "f"(x)); return y;
}
__device__ __forceinline__ unsigned long long mul2(unsigned long long a, unsigned long long b) {
    unsigned long long d; asm("mul.rn.f32x2 %0, %1, %2;" : "=l"(d) : "l"(a), "l"(b)); return d;
}
__device__ __forceinline__ unsigned long long fma2(unsigned long long a, unsigned long long b, unsigned long long c) {
    unsigned long long d; asm("fma.rn.f32x2 %0, %1, %2, %3;" : "=l"(d) : "l"(a), "l"(b), "l"(c)); return d;
}
__device__ __forceinline__ unsigned long long add2(unsigned long long a, unsigned long long b) {
    unsigned long long d; asm("add.rn.f32x2 %0, %1, %2;" : "=l"(d) : "l"(a), "l"(b)); return d;
}
__device__ __forceinline__ unsigned long long packf2(float lo, float hi) {
    unsigned long long d; asm("mov.b64 %0, {%1, %2};" : "=l"(d) : "f"(lo), "f"(hi)); return d;
}
__device__ __forceinline__ float2 unpackf2(unsigned long long p) {
    float lo, hi; asm("mov.b64 {%0, %1}, %2;" : "=f"(lo), "=f"(hi) : "l"(p));
    return make_float2(lo, hi);
}

__global__ __launch_bounds__(32) void rnn_scan_kernel(
    const float* __restrict__ x,      // [B, T, 1]
    const float* __restrict__ w_ih,   // [H]
    const float* __restrict__ w_hh,   // [H, H]
    const float* __restrict__ b_ih,   // [H]
    const float* __restrict__ b_hh,   // [H]
    const float* __restrict__ w_fc,   // [H]
    const float* __restrict__ b_fc,   // [1]
    float* __restrict__ out)          // [B]
{
    __shared__ __align__(16) float sx[4 * XROW];  // 4 sequences of x (~8.3KB)

    const int warp = blockIdx.x;      // one warp per block
    const int lane = threadIdx.x;     // 0..31
    const int g    = lane >> 3;       // element within warp (0..3)
    const int m    = lane & 7;        // lane within 8-lane group

    const int e  = warp * 4 + g;      // batch element, < 4096
    const int j0 = 2 * m;             // first owned row
    const int j1 = 2 * m + 1;         // second owned row
    const int mp = m ^ 4;             // exchange partner within the group
    const int j0p = 2 * mp;           // partner's rows
    const int j1p = 2 * mp + 1;
    const int half = m & 4;           // 0 -> pairs 0..3, 4 -> pairs 4..7
    const int col0 = 2 * half;        // first h-column of my half (0 or 8)

    // ---- Preload this warp's 4 contiguous x sequences (8KB) into smem. ----
    {
        const float4* src = reinterpret_cast<const float4*>(x + (long)warp * 4 * RNN_T);
        #pragma unroll
        for (int i = 0; i < 16; i++) {
            const int idx = i * 32 + lane;        // float4 index 0..511
            const float4 v = src[idx];
            const int f   = idx * 4;
            const int row = f >> 9;               // /512
            const int col = f & 511;
            *reinterpret_cast<float4*>(&sx[row * XROW + col]) = v;
        }
    }
    __syncwarp();

    // Packed weights over MY half-columns [col0, col0+8) for 4 rows:
    // own rows j0,j1 and partner rows j0p,j1p.
    unsigned long long wO0[4], wO1[4], wP0[4], wP1[4];
    {
        const float4* r0 = reinterpret_cast<const float4*>(w_hh + j0  * RNN_H + col0);
        const float4* r1 = reinterpret_cast<const float4*>(w_hh + j1  * RNN_H + col0);
        const float4* r2 = reinterpret_cast<const float4*>(w_hh + j0p * RNN_H + col0);
        const float4* r3 = reinterpret_cast<const float4*>(w_hh + j1p * RNN_H + col0);
        #pragma unroll
        for (int q = 0; q < 2; q++) {
            float4 a = r0[q], b = r1[q], c = r2[q], d = r3[q];
            wO0[q * 2 + 0] = packf2(a.x, a.y); wO0[q * 2 + 1] = packf2(a.z, a.w);
            wO1[q * 2 + 0] = packf2(b.x, b.y); wO1[q * 2 + 1] = packf2(b.z, b.w);
            wP0[q * 2 + 0] = packf2(c.x, c.y); wP0[q * 2 + 1] = packf2(c.z, c.w);
            wP1[q * 2 + 0] = packf2(d.x, d.y); wP1[q * 2 + 1] = packf2(d.z, d.w);
        }
    }
    const float wih0  = w_ih[j0];
    const float wih1  = w_ih[j1];
    const float bias0 = b_ih[j0] + b_hh[j0];
    const float bias1 = b_ih[j1] + b_hh[j1];

    // Gather sources (hoisted registers; reg-source SHFL.IDX).
    const int s0 = half + 0, s1 = half + 1, s2 = half + 2, s3 = half + 3;

    const float4* sx4 = reinterpret_cast<const float4*>(&sx[g * XROW]);

    // Lane state: packed (h_j0, h_j1) f32x2 — also the shuffle payload.
    unsigned long long hq = packf2(0.0f, 0.0f);

    #pragma unroll 1
    for (int t4 = 0; t4 < RNN_T / 4; t4++) {
        const float4 xv = sx4[t4];    // broadcast LDS.128 within each group
        const float xs[4] = {xv.x, xv.y, xv.z, xv.w};

        // Hoisted seeds (pure f(x), off the h-chain).
        float sd0[4], sd1[4];
        #pragma unroll
        for (int s = 0; s < 4; s++) {
            sd0[s] = fmaf(xs[s], wih0, bias0);
            sd1[s] = fmaf(xs[s], wih1, bias1);
        }

        #pragma unroll
        for (int s = 0; s < 4; s++) {
            // Half-gather: 4 reg-source 64-bit shuffles (8 SHFL.32).
            const unsigned long long p0 = __shfl_sync(0xffffffffu, hq, s0, 8);
            const unsigned long long p1 = __shfl_sync(0xffffffffu, hq, s1, 8);
            const unsigned long long p2 = __shfl_sync(0xffffffffu, hq, s2, 8);
            const unsigned long long p3 = __shfl_sync(0xffffffffu, hq, s3, 8);

            // Partner-row partials FIRST (they gate the exchange).
            unsigned long long c0 = mul2(wP0[0], p0);
            unsigned long long d0 = mul2(wP1[0], p0);
            unsigned long long c1 = mul2(wP0[1], p1);
            unsigned long long d1 = mul2(wP1[1], p1);
            c0 = fma2(wP0[2], p2, c0);
            d0 = fma2(wP1[2], p2, d0);
            c1 = fma2(wP0[3], p3, c1);
            d1 = fma2(wP1[3], p3, d1);
            const float2 pc = unpackf2(add2(c0, c1));
            const float2 pd = unpackf2(add2(d0, d1));
            const unsigned long long sendP = packf2(pc.x + pc.y, pd.x + pd.y);

            // One 64-bit butterfly exchange (immediate lane, 2 SHFL.32).
            const unsigned long long recvP = __shfl_xor_sync(0xffffffffu, sendP, 4, 8);

            // Own-row partials (overlap the exchange latency), seeded.
            unsigned long long a0 = fma2(wO0[0], p0, packf2(sd0[s], 0.0f));
            unsigned long long b0 = fma2(wO1[0], p0, packf2(sd1[s], 0.0f));
            unsigned long long a1 = mul2(wO0[1], p1);
            unsigned long long b1 = mul2(wO1[1], p1);
            a0 = fma2(wO0[2], p2, a0);
            b0 = fma2(wO1[2], p2, b0);
            a1 = fma2(wO0[3], p3, a1);
            b1 = fma2(wO1[3], p3, b1);
            const float2 pa = unpackf2(add2(a0, a1));
            const float2 pb = unpackf2(add2(b0, b1));
            const float own0 = pa.x + pa.y;
            const float own1 = pb.x + pb.y;

            // Merge halves and activate.
            const float2 rv = unpackf2(recvP);
            const float h0 = tanh_approx(own0 + rv.x);
            const float h1 = tanh_approx(own1 + rv.y);
            hq = packf2(h0, h1);
        }
    }

    // out[e] = sum_j h[j]*w_fc[j] + b_fc  (reduce over the 8-lane group)
    const float2 hf = unpackf2(hq);
    float v = hf.x * w_fc[j0] + hf.y * w_fc[j1];
    #pragma unroll
    for (int off = 4; off; off >>= 1)
        v += __shfl_xor_sync(0xffffffffu, v, off, 8);
    if (m == 0)
        out[e] = v + b_fc[0];
}

extern "C" void kernel_launch(void* const* d_in, const int* in_sizes, int n_in,
                              void* d_out, int out_size) {
    const float* x    = (const float*)d_in[0];
    const float* w_ih = (const float*)d_in[1];
    const float* w_hh = (const float*)d_in[2];
    const float* b_ih = (const float*)d_in[3];
    const float* b_hh = (const float*)d_in[4];
    const float* w_fc = (const float*)d_in[5];
    const float* b_fc = (const float*)d_in[6];
    float* out = (float*)d_out;

    // 1024 single-warp blocks; 4 batch elements per warp, 8 lanes each.
    rnn_scan_kernel<<<RNN_B / 4, 32>>>(x, w_ih, w_hh, b_ih, b_hh, w_fc, b_fc, out);
}

// round 16
// speedup vs baseline: 1.0591x; 1.0591x over previous
#include <cuda_runtime.h>

// RNN: B=4096, T=512, I=1, H=16, O=1
//   h_t = tanh(x_t*w_ih + b_ih + b_hh + W_hh h_{t-1}), h_0=0
//   out[b] = dot(h_T, w_fc) + b_fc
//
// R16: 4-lane groups. R15 proved SHFL throughput was NOT the binder and
// that 16 SHFL.32/warp-step is the information floor for full-row work.
// With 4 lanes/element (lane owns rows {4m..4m+3}, state = 2 packed f32x2)
// the SAME 16-SHFL.32 gather (8 immediate width-4 64-bit shuffles, single
// generation) serves EIGHT elements -> per-element shuffle cost halves,
// SM-wide MIO pressure halves (512 warps), chain stays one-generation.
// fma work/warp-step doubles (32 fma2) -> fma issue floor ~98cy, below
// R14's C=172.
// Kept: f32 datapath, packed f32x2 trees, tanh.approx.f32, x in smem.

#define RNN_B 4096
#define RNN_T 512
#define RNN_H 16
#define XROW (RNN_T + 4)   // x row pad: 8 groups' reads land on distinct banks

__device__ __forceinline__ float tanh_approx(float x) {
    float y; asm("tanh.approx.f32 %0, %1;" : "=f"(y) : "f"(x)); return y;
}
__device__ __forceinline__ unsigned long long mul2(unsigned long long a, unsigned long long b) {
    unsigned long long d; asm("mul.rn.f32x2 %0, %1, %2;" : "=l"(d) : "l"(a), "l"(b)); return d;
}
__device__ __forceinline__ unsigned long long fma2(unsigned long long a, unsigned long long b, unsigned long long c) {
    unsigned long long d; asm("fma.rn.f32x2 %0, %1, %2, %3;" : "=l"(d) : "l"(a), "l"(b), "l"(c)); return d;
}
__device__ __forceinline__ unsigned long long add2(unsigned long long a, unsigned long long b) {
    unsigned long long d; asm("add.rn.f32x2 %0, %1, %2;" : "=l"(d) : "l"(a), "l"(b)); return d;
}
__device__ __forceinline__ unsigned long long packf2(float lo, float hi) {
    unsigned long long d; asm("mov.b64 %0, {%1, %2};" : "=l"(d) : "f"(lo), "f"(hi)); return d;
}
__device__ __forceinline__ float2 unpackf2(unsigned long long p) {
    float lo, hi; asm("mov.b64 {%0, %1}, %2;" : "=f"(lo), "=f"(hi) : "l"(p));
    return make_float2(lo, hi);
}

__global__ __launch_bounds__(32) void rnn_scan_kernel(
    const float* __restrict__ x,      // [B, T, 1]
    const float* __restrict__ w_ih,   // [H]
    const float* __restrict__ w_hh,   // [H, H]
    const float* __restrict__ b_ih,   // [H]
    const float* __restrict__ b_hh,   // [H]
    const float* __restrict__ w_fc,   // [H]
    const float* __restrict__ b_fc,   // [1]
    float* __restrict__ out)          // [B]
{
    __shared__ __align__(16) float sx[8 * XROW];  // 8 sequences of x (~16.5KB)

    const int warp = blockIdx.x;      // one warp per block
    const int lane = threadIdx.x;     // 0..31
    const int g    = lane >> 2;       // element within warp (0..7)
    const int m    = lane & 3;        // lane within 4-lane group

    const int e  = warp * 8 + g;      // batch element, < 4096
    const int j0 = 4 * m;             // owned rows j0..j0+3

    // ---- Preload this warp's 8 contiguous x sequences (16KB) into smem. ----
    {
        const float4* src = reinterpret_cast<const float4*>(x + (long)warp * 8 * RNN_T);
        #pragma unroll
        for (int i = 0; i < 32; i++) {
            const int idx = i * 32 + lane;        // float4 index 0..1023
            const float4 v = src[idx];
            const int f   = idx * 4;
            const int row = f >> 9;               // /512 -> sequence 0..7
            const int col = f & 511;
            *reinterpret_cast<float4*>(&sx[row * XROW + col]) = v;
        }
    }
    __syncwarp();

    // Packed weights: 4 owned rows x 8 pair-columns.
    // wr[i][k] = (w[j0+i][2k], w[j0+i][2k+1])
    unsigned long long wr[4][8];
    float wih[4], bias[4];
    #pragma unroll
    for (int i = 0; i < 4; i++) {
        const float4* w4 = reinterpret_cast<const float4*>(w_hh + (j0 + i) * RNN_H);
        #pragma unroll
        for (int q = 0; q < 4; q++) {
            float4 rw = w4[q];
            wr[i][q * 2 + 0] = packf2(rw.x, rw.y);
            wr[i][q * 2 + 1] = packf2(rw.z, rw.w);
        }
        wih[i]  = w_ih[j0 + i];
        bias[i] = b_ih[j0 + i] + b_hh[j0 + i];
    }

    const float4* sx4 = reinterpret_cast<const float4*>(&sx[g * XROW]);

    // Lane state: rows {4m..4m+3} as two packed f32x2.
    unsigned long long hq0 = packf2(0.0f, 0.0f);
    unsigned long long hq1 = packf2(0.0f, 0.0f);

    #pragma unroll 1
    for (int t4 = 0; t4 < RNN_T / 4; t4++) {
        const float4 xv = sx4[t4];    // broadcast LDS.128 within each group
        const float xs[4] = {xv.x, xv.y, xv.z, xv.w};

        #pragma unroll
        for (int s = 0; s < 4; s++) {
            // Seeds for the 4 owned rows (pure f(x), off the h-chain).
            const unsigned long long sd0 = packf2(fmaf(xs[s], wih[0], bias[0]), 0.0f);
            const unsigned long long sd1 = packf2(fmaf(xs[s], wih[1], bias[1]), 0.0f);
            const unsigned long long sd2 = packf2(fmaf(xs[s], wih[2], bias[2]), 0.0f);
            const unsigned long long sd3 = packf2(fmaf(xs[s], wih[3], bias[3]), 0.0f);

            // Single-generation gather: all 16 h as 8 packed pairs from the
            // 4 lanes of the group (immediate width-4 shuffles).
            // p[2k]   = (h_{4k},   h_{4k+1})  = lane k's hq0
            // p[2k+1] = (h_{4k+2}, h_{4k+3})  = lane k's hq1
            const unsigned long long p0 = __shfl_sync(0xffffffffu, hq0, 0, 4);
            const unsigned long long p1 = __shfl_sync(0xffffffffu, hq1, 0, 4);
            const unsigned long long p2 = __shfl_sync(0xffffffffu, hq0, 1, 4);
            const unsigned long long p3 = __shfl_sync(0xffffffffu, hq1, 1, 4);
            const unsigned long long p4 = __shfl_sync(0xffffffffu, hq0, 2, 4);
            const unsigned long long p5 = __shfl_sync(0xffffffffu, hq1, 2, 4);
            const unsigned long long p6 = __shfl_sync(0xffffffffu, hq0, 3, 4);
            const unsigned long long p7 = __shfl_sync(0xffffffffu, hq1, 3, 4);

            // Four row-trees, 2 accumulators each, late-merged on p7.
            unsigned long long a0 = fma2(wr[0][0], p0, sd0);
            unsigned long long a1 = mul2(wr[0][1], p1);
            unsigned long long b0 = fma2(wr[1][0], p0, sd1);
            unsigned long long b1 = mul2(wr[1][1], p1);
            unsigned long long c0 = fma2(wr[2][0], p0, sd2);
            unsigned long long c1 = mul2(wr[2][1], p1);
            unsigned long long d0 = fma2(wr[3][0], p0, sd3);
            unsigned long long d1 = mul2(wr[3][1], p1);

            a0 = fma2(wr[0][2], p2, a0);  a1 = fma2(wr[0][3], p3, a1);
            b0 = fma2(wr[1][2], p2, b0);  b1 = fma2(wr[1][3], p3, b1);
            c0 = fma2(wr[2][2], p2, c0);  c1 = fma2(wr[2][3], p3, c1);
            d0 = fma2(wr[3][2], p2, d0);  d1 = fma2(wr[3][3], p3, d1);

            a0 = fma2(wr[0][4], p4, a0);  a1 = fma2(wr[0][5], p5, a1);
            b0 = fma2(wr[1][4], p4, b0);  b1 = fma2(wr[1][5], p5, b1);
            c0 = fma2(wr[2][4], p4, c0);  c1 = fma2(wr[2][5], p5, c1);
            d0 = fma2(wr[3][4], p4, d0);  d1 = fma2(wr[3][5], p5, d1);

            a0 = fma2(wr[0][6], p6, a0);  a1 = fma2(wr[0][7], p7, a1);
            b0 = fma2(wr[1][6], p6, b0);  b1 = fma2(wr[1][7], p7, b1);
            c0 = fma2(wr[2][6], p6, c0);  c1 = fma2(wr[2][7], p7, c1);
            d0 = fma2(wr[3][6], p6, d0);  d1 = fma2(wr[3][7], p7, d1);

            const float2 fa = unpackf2(add2(a0, a1));
            const float2 fb = unpackf2(add2(b0, b1));
            const float2 fc = unpackf2(add2(c0, c1));
            const float2 fd = unpackf2(add2(d0, d1));

            const float h0 = tanh_approx(fa.x + fa.y);
            const float h1 = tanh_approx(fb.x + fb.y);
            const float h2 = tanh_approx(fc.x + fc.y);
            const float h3 = tanh_approx(fd.x + fd.y);
            hq0 = packf2(h0, h1);
            hq1 = packf2(h2, h3);
        }
    }

    // out[e] = sum_j h[j]*w_fc[j] + b_fc  (reduce over the 4-lane group)
    const float2 u0 = unpackf2(hq0);
    const float2 u1 = unpackf2(hq1);
    float v = u0.x * w_fc[j0] + u0.y * w_fc[j0 + 1]
            + u1.x * w_fc[j0 + 2] + u1.y * w_fc[j0 + 3];
    v += __shfl_xor_sync(0xffffffffu, v, 1, 4);
    v += __shfl_xor_sync(0xffffffffu, v, 2, 4);
    if (m == 0)
        out[e] = v + b_fc[0];
}

extern "C" void kernel_launch(void* const* d_in, const int* in_sizes, int n_in,
                              void* d_out, int out_size) {
    const float* x    = (const float*)d_in[0];
    const float* w_ih = (const float*)d_in[1];
    const float* w_hh = (const float*)d_in[2];
    const float* b_ih = (const float*)d_in[3];
    const float* b_hh = (const float*)d_in[4];
    const float* w_fc = (const float*)d_in[5];
    const float* b_fc = (const float*)d_in[6];
    float* out = (float*)d_out;

    // 512 single-warp blocks; 8 batch elements per warp, 4 lanes each.
    rnn_scan_kernel<<<RNN_B / 8, 32>>>(x, w_ih, w_hh, b_ih, b_hh, w_fc, b_fc, out);
}